// round 16
// baseline (speedup 1.0000x reference)
#include <cuda_runtime.h>
#include <cuda_fp16.h>
#include <cstdint>
#include <math.h>

#define HH 256
#define WW 256
#define HWTOT 65536

// ===================== device scratch =====================
__device__ __align__(256) __half g_xp[33816576];    // 2 * 4*256*258*64   [s][b][h][w0..257][ci]
__device__ __align__(256) __half g_q1p[135266304];  // 2 * 4*256*258*256
__device__ __align__(256) float  g_q2[67108864];    // planar (4,256,256,256)
__device__ __align__(256) __half g_w1s[294912];     // 2 * 9*256*64   [s][chunk64][co][ci64]
__device__ __align__(256) __half g_w2s[1179648];    // 2 * 36*256*64
__device__ float g_M2t[256 * 16];   // M2t[ci][k]
__device__ float g_c0[16];
__device__ float g_mu2[16];

// ===================== helpers =====================
__device__ __forceinline__ uint32_t smem_u32(const void* p) {
    uint32_t a;
    asm("{ .reg .u64 t; cvta.to.shared.u64 t, %1; cvt.u32.u64 %0, t; }" : "=r"(a) : "l"(p));
    return a;
}
__device__ __forceinline__ uint32_t swz128(uint32_t o) { return o ^ ((o >> 3) & 0x70); }

__device__ __forceinline__ void cp_async16(uint32_t dst, const void* src) {
    asm volatile("cp.async.cg.shared.global [%0], [%1], 16;" :: "r"(dst), "l"(src) : "memory");
}
#define CP_COMMIT() asm volatile("cp.async.commit_group;" ::: "memory")
#define CP_WAIT(n)  asm volatile("cp.async.wait_group %0;" :: "n"(n) : "memory")

#define LDSM_X4(r0, r1, r2, r3, addr) \
    asm volatile("ldmatrix.sync.aligned.m8n8.x4.shared.b16 {%0,%1,%2,%3}, [%4];" \
                 : "=r"(r0), "=r"(r1), "=r"(r2), "=r"(r3) : "r"(addr))

#define MMA16816(d, a, b0, b1) \
    asm volatile("mma.sync.aligned.m16n8k16.row.col.f32.f16.f16.f32 " \
                 "{%0,%1,%2,%3}, {%4,%5,%6,%7}, {%8,%9}, {%0,%1,%2,%3};" \
                 : "+f"((d)[0]), "+f"((d)[1]), "+f"((d)[2]), "+f"((d)[3]) \
                 : "r"((a)[0]), "r"((a)[1]), "r"((a)[2]), "r"((a)[3]), "r"(b0), "r"(b1))

__device__ __forceinline__ void split2(float v, __half& h0, __half& h1) {
    h0 = __float2half_rn(v);
    float r = v - __half2float(h0);
    h1 = __float2half_rn(r);
}
__device__ __forceinline__ uint32_t packh(__half lo, __half hi) {
    unsigned short a = *reinterpret_cast<unsigned short*>(&lo);
    unsigned short b = *reinterpret_cast<unsigned short*>(&hi);
    return (uint32_t)a | ((uint32_t)b << 16);
}

// ===================== merged prep: head tables + x split + w1/w2 split =====================
// grid 3920 blocks x 256:
//   [0,16)        : M2t (+ block 0: c0/mu2)
//   [16,1040)     : x split
//   [1040,1616)   : w1 split  (147456 elems)
//   [1616,3920)   : w2 split  (589824 elems)
__device__ __forceinline__ void prep_w_body(const float* __restrict__ w,
                                            __half* __restrict__ dst, int gid, int CIN) {
    const int NCC = CIN / 64;
    const size_t WPLANE = (size_t)256 * CIN * 9;
    if (gid >= (int)WPLANE) return;
    int tap = gid % 9, r = gid / 9;
    int ci = r % CIN, co = r / CIN;
    int dr = tap / 3, dc = tap % 3;
    int cic = ci >> 6, cj = ci & 63;
    int chunk = (dr * NCC + cic) * 3 + dc;
    size_t di = ((size_t)chunk * 256 + co) * 64 + cj;
    __half s0, s1;
    split2(w[gid], s0, s1);
    dst[di] = s0;
    dst[di + WPLANE] = s1;
}

__global__ void prep_all(const float* __restrict__ x,
                         const float* __restrict__ w1,
                         const float* __restrict__ w2,
                         const float* __restrict__ w3,
                         const float* __restrict__ b3,
                         const float* __restrict__ mu) {
    const int bx = blockIdx.x;
    const int tid = threadIdx.x;
    if (bx < 16) {
        const int p = bx * 256 + tid;  // p = ci*16 + k
        const int ci = p >> 4, k = p & 15;
        float s = 0.f;
        for (int co = 0; co < 256; ++co) s = fmaf(mu[k * 256 + co], w3[co * 256 + ci], s);
        g_M2t[p] = s;
        if (bx == 0 && tid < 16) {
            float sb = 0.f, m2 = 0.f;
            for (int c = 0; c < 256; ++c) {
                float mv = mu[tid * 256 + c];
                sb = fmaf(mv, b3[c], sb);
                m2 = fmaf(mv, mv, m2);
            }
            g_c0[tid] = sb;
            g_mu2[tid] = m2;
        }
    } else if (bx < 1040) {
        const int id = bx - 16;
        const int h = id & 255, b = id >> 8;
        const size_t XPLANE = 16908288;  // 4*256*258*64
        for (int idx = tid; idx < 258 * 64; idx += 256) {
            int w = idx >> 6, ci = idx & 63;
            int wsrc = min(max(w - 1, 0), WW - 1);
            float v = x[(((size_t)b * 64 + ci) * HH + h) * WW + wsrc];
            __half s0, s1;
            split2(v, s0, s1);
            size_t base = (((size_t)b * 256 + h) * 258 + w) * 64 + ci;
            g_xp[base] = s0;
            g_xp[base + XPLANE] = s1;
        }
    } else if (bx < 1616) {
        prep_w_body(w1, g_w1s, (bx - 1040) * 256 + tid, 64);
    } else {
        prep_w_body(w2, g_w2s, (bx - 1616) * 256 + tid, 256);
    }
}

// ===================== conv via mma.sync (fp16 2-split, 3 products) — R7 verbatim =====================
// grid (4 = 2 pxHalf x 2 coHalf, 256 h, 4 b), 256 threads (8 warps: 4M x 2N).
// K-chunks of 32ci, plane-packed rows [p0 32ci | p1 32ci]; ring-of-3 32KB buffers
// -> 2 CTAs/SM.  One __syncthreads per chunk.  ALL staging .cg.
template <int CIN, bool SPLIT_OUT>
__global__ __launch_bounds__(256, 2) void conv_mma(
    const __half* __restrict__ xp,   // [s][b][h][258][CIN]
    const __half* __restrict__ wsp,  // [s][chunk64][256][64]
    const float* __restrict__ bias,
    __half* __restrict__ out_split,  // [s][b][h][258][256]
    float* __restrict__ out_planar)  // [b][co][h][w]
{
    constexpr int NCC64 = CIN / 64;
    constexpr int NCC32 = CIN / 32;
    constexpr int NCH = 9 * NCC32;   // 18 or 72 chunks
    const size_t IPLANE = (size_t)4 * 256 * 258 * CIN;
    const size_t WPLANE = (size_t)(9 * NCC64) * 16384;
    const size_t OPLANE = (size_t)4 * 256 * 258 * 256;
    constexpr uint32_t BUFB = 32768;  // 16KB A + 16KB B

    extern __shared__ char smem_raw[];
    const uint32_t abase = (smem_u32(smem_raw) + 1023u) & ~1023u;

    const int tid = threadIdx.x;
    const int wid = tid >> 5, lane = tid & 31;
    const int warpM = wid & 3, warpN = wid >> 2;
    const int h = blockIdx.y, b = blockIdx.z;
    const int pxBase = (blockIdx.x & 1) * 128;
    const int coBase = (blockIdx.x >> 1) * 128;

    // stage one 32ci chunk (A + B), plane-packed rows
    auto stage = [&](int chunk, int buf) {
        int dc = chunk % 3;
        int r0 = chunk / 3;
        int cic32 = r0 % NCC32;
        int dr = r0 / NCC32;
        int hr = min(max(h + dr - 1, 0), HH - 1);
        const __half* xrow =
            xp + (((size_t)b * 256 + hr) * 258 + pxBase + dc) * CIN + cic32 * 32;
        uint32_t aoff = abase + (uint32_t)buf * BUFB;
        uint32_t boff = aoff + 16384;
#pragma unroll
        for (int t = 0; t < 4; ++t) {
            int idx = tid + (t << 8);
            int row = idx >> 3, sub = idx & 7;
            int plane = sub >> 2, seg = sub & 3;
            const void* src = xrow + (size_t)plane * IPLANE + (size_t)row * CIN + seg * 8;
            cp_async16(aoff + swz128((row << 7) | (plane << 6) | (seg << 4)), src);
        }
        int chunk64 = (dr * NCC64 + (cic32 >> 1)) * 3 + dc;
        const __half* wrow =
            wsp + ((size_t)chunk64 * 256 + coBase) * 64 + (cic32 & 1) * 32;
#pragma unroll
        for (int t = 0; t < 4; ++t) {
            int idx = tid + (t << 8);
            int co = idx >> 3, sub = idx & 7;
            int plane = sub >> 2, seg = sub & 3;
            const void* src = wrow + (size_t)plane * WPLANE + (size_t)co * 64 + seg * 8;
            cp_async16(boff + swz128((co << 7) | (plane << 6) | (seg << 4)), src);
        }
        CP_COMMIT();
    };

    float acc[2][8][4];
#pragma unroll
    for (int mt = 0; mt < 2; ++mt)
#pragma unroll
        for (int nt = 0; nt < 8; ++nt)
#pragma unroll
            for (int e = 0; e < 4; ++e) acc[mt][nt][e] = 0.f;

    const uint32_t rA = lane & 15, cA = (lane >> 4) << 4;
    const uint32_t rB = (lane & 7) | ((lane >> 4) << 3), cB = ((lane >> 3) & 1) << 4;

    // products: (a0,b0), (a0,b1), (a1,b0)
    const int SA[3] = {0, 0, 1};
    const int SB[3] = {0, 1, 0};

    stage(0, 0);
    stage(1, 1);

    for (int c = 0; c < NCH; ++c) {
        if (c + 1 < NCH) { CP_WAIT(1); } else { CP_WAIT(0); }
        __syncthreads();
        if (c + 2 < NCH) stage(c + 2, (c + 2) - ((c + 2) / 3) * 3);

        const uint32_t aB = abase + (uint32_t)(c - (c / 3) * 3) * BUFB;
        const uint32_t bB = aB + 16384;

#pragma unroll
        for (int ks = 0; ks < 2; ++ks) {
            uint32_t af[2][2][4];
#pragma unroll
            for (int plane = 0; plane < 2; ++plane)
#pragma unroll
                for (int mt = 0; mt < 2; ++mt) {
                    uint32_t row = warpM * 32 + mt * 16 + rA;
                    uint32_t addr =
                        aB + swz128((row << 7) + (plane << 6) + ks * 32 + cA);
                    LDSM_X4(af[plane][mt][0], af[plane][mt][1], af[plane][mt][2],
                            af[plane][mt][3], addr);
                }
#pragma unroll
            for (int np = 0; np < 4; ++np) {
                uint32_t bfr[2][4];
#pragma unroll
                for (int plane = 0; plane < 2; ++plane) {
                    uint32_t row = warpN * 64 + np * 16 + rB;
                    uint32_t addr =
                        bB + swz128((row << 7) + (plane << 6) + ks * 32 + cB);
                    LDSM_X4(bfr[plane][0], bfr[plane][1], bfr[plane][2], bfr[plane][3],
                            addr);
                }
#pragma unroll
                for (int t = 0; t < 3; ++t) {
                    const int sa = SA[t], sb = SB[t];
#pragma unroll
                    for (int mt = 0; mt < 2; ++mt) {
                        MMA16816(acc[mt][2 * np], af[sa][mt], bfr[sb][0], bfr[sb][1]);
                        MMA16816(acc[mt][2 * np + 1], af[sa][mt], bfr[sb][2], bfr[sb][3]);
                    }
                }
            }
        }
    }

    // ---- epilogue (R7-proven) ----
    float bv0[8], bv1[8];
#pragma unroll
    for (int nt = 0; nt < 8; ++nt) {
        int c0 = coBase + warpN * 64 + nt * 8 + (lane & 3) * 2;
        bv0[nt] = __ldg(bias + c0);
        bv1[nt] = __ldg(bias + c0 + 1);
    }

#pragma unroll
    for (int mt = 0; mt < 2; ++mt) {
#pragma unroll
        for (int nt = 0; nt < 8; ++nt) {
            int px0 = pxBase + warpM * 32 + mt * 16 + (lane >> 2);
            int c0 = coBase + warpN * 64 + nt * 8 + (lane & 3) * 2;
#pragma unroll
            for (int half = 0; half < 2; ++half) {
                int px = px0 + half * 8;
                float v0 = fmaxf(acc[mt][nt][2 * half] + bv0[nt], 0.f);
                float v1 = fmaxf(acc[mt][nt][2 * half + 1] + bv1[nt], 0.f);
                if (SPLIT_OUT) {
                    __half a0, a1, d0, d1;
                    split2(v0, a0, a1);
                    split2(v1, d0, d1);
                    uint32_t p0 = packh(a0, d0), p1 = packh(a1, d1);
                    size_t base = (((size_t)b * 256 + h) * 258 + px + 1) * 256 + c0;
                    *reinterpret_cast<uint32_t*>(out_split + base) = p0;
                    *reinterpret_cast<uint32_t*>(out_split + OPLANE + base) = p1;
                    if (px == 0 || px == 255) {
                        size_t hb =
                            (((size_t)b * 256 + h) * 258 + (px == 0 ? 0 : 257)) * 256 + c0;
                        *reinterpret_cast<uint32_t*>(out_split + hb) = p0;
                        *reinterpret_cast<uint32_t*>(out_split + OPLANE + hb) = p1;
                    }
                } else {
                    size_t o0 = ((size_t)b * 256 + c0) * HWTOT + h * WW + px;
                    out_planar[o0] = v0;
                    out_planar[o0 + HWTOT] = v1;
                }
            }
        }
    }
}

// ===================== head: cross-only + softmax (R7-proven; grid.x == 128) ==========
__global__ __launch_bounds__(256) void cross_head(
    const float* __restrict__ label, float* __restrict__ out)
{
    __shared__ __align__(16) float m2s[256][16];
    __shared__ float c2s[16], labs[16];

    const int tid = threadIdx.x;
    const int b = blockIdx.y;
    const int px0 = blockIdx.x * 512 + tid * 2;

    for (int i = tid; i < 4096; i += 256) m2s[i >> 4][i & 15] = g_M2t[i];
    if (tid < 16) {
        c2s[tid] = 2.f * g_c0[tid] - g_mu2[tid];
        labs[tid] = label[tid];
    }
    __syncthreads();

    const float* q2b = g_q2 + (size_t)b * 256 * HWTOT + px0;

    float acc[16][2];
#pragma unroll
    for (int k = 0; k < 16; ++k) acc[k][0] = acc[k][1] = 0.f;

#pragma unroll 4
    for (int ci = 0; ci < 256; ++ci) {
        float2 v = *reinterpret_cast<const float2*>(q2b + (size_t)ci * HWTOT);
        float4 m0 = *reinterpret_cast<const float4*>(&m2s[ci][0]);
        float4 m1 = *reinterpret_cast<const float4*>(&m2s[ci][4]);
        float4 m2v = *reinterpret_cast<const float4*>(&m2s[ci][8]);
        float4 m3 = *reinterpret_cast<const float4*>(&m2s[ci][12]);
        float mm[16] = {m0.x, m0.y, m0.z, m0.w, m1.x, m1.y, m1.z, m1.w,
                        m2v.x, m2v.y, m2v.z, m2v.w, m3.x, m3.y, m3.z, m3.w};
#pragma unroll
        for (int k = 0; k < 16; ++k) {
            acc[k][0] = fmaf(v.x, mm[k], acc[k][0]);
            acc[k][1] = fmaf(v.y, mm[k], acc[k][1]);
        }
    }

#pragma unroll
    for (int j = 0; j < 2; ++j) {
        float lg[16];
        float mx = -1e30f;
#pragma unroll
        for (int k = 0; k < 16; ++k) {
            lg[k] = fmaf(2.f, acc[k][j], c2s[k]);
            mx = fmaxf(mx, lg[k]);
        }
        float se = 0.f, sl = 0.f;
#pragma unroll
        for (int k = 0; k < 16; ++k) {
            float e = __expf(lg[k] - mx);
            se += e;
            sl = fmaf(e, labs[k], sl);
        }
        out[(size_t)b * HWTOT + px0 + j] = sl / se;
    }
}

// ===================== launch =====================
extern "C" void kernel_launch(void* const* d_in, const int* in_sizes, int n_in,
                              void* d_out, int out_size) {
    const float* x = (const float*)d_in[0];
    const float* w1 = (const float*)d_in[1];
    const float* b1 = (const float*)d_in[2];
    const float* w2 = (const float*)d_in[3];
    const float* b2 = (const float*)d_in[4];
    const float* w3 = (const float*)d_in[5];
    const float* b3 = (const float*)d_in[6];
    const float* mu = (const float*)d_in[7];
    const float* label = (const float*)d_in[8];
    float* out = (float*)d_out;

    __half *xp, *q1p, *w1s, *w2s;
    float* q2;
    cudaGetSymbolAddress((void**)&xp, g_xp);
    cudaGetSymbolAddress((void**)&q1p, g_q1p);
    cudaGetSymbolAddress((void**)&q2, g_q2);
    cudaGetSymbolAddress((void**)&w1s, g_w1s);
    cudaGetSymbolAddress((void**)&w2s, g_w2s);

    const int SMEM_BYTES = 3 * 32768 + 1024;  // 97 KB -> 2 CTAs/SM
    cudaFuncSetAttribute(conv_mma<64, true>, cudaFuncAttributeMaxDynamicSharedMemorySize,
                         SMEM_BYTES);
    cudaFuncSetAttribute(conv_mma<256, false>, cudaFuncAttributeMaxDynamicSharedMemorySize,
                         SMEM_BYTES);

    prep_all<<<3920, 256>>>(x, w1, w2, w3, b3, mu);

    dim3 cgrid(4, 256, 4);
    conv_mma<64, true><<<cgrid, 256, SMEM_BYTES>>>(xp, w1s, b1, q1p, nullptr);
    conv_mma<256, false><<<cgrid, 256, SMEM_BYTES>>>(q1p, w2s, b2, nullptr, q2);

    cross_head<<<dim3(128, 4), 256>>>(label, out);  // 128 * 512 px == HWTOT
}

// round 17
// speedup vs baseline: 1.5692x; 1.5692x over previous
#include <cuda_runtime.h>
#include <cuda_fp16.h>
#include <cstdint>
#include <math.h>

#define HH 256
#define WW 256
#define HWTOT 65536

// ===================== device scratch =====================
__device__ __align__(256) __half g_xp[33816576];    // 2 * 4*256*258*64   [s][b][h][w0..257][ci]
__device__ __align__(256) __half g_q1p[135266304];  // 2 * 4*256*258*256
__device__ __align__(256) float  g_q2[67108864];    // planar (4,256,256,256)
__device__ __align__(256) __half g_w1s[294912];     // 2 * 9*256*64   [s][chunk64][co][ci64]
__device__ __align__(256) __half g_w2s[1179648];    // 2 * 36*256*64
__device__ float g_M2t[256 * 16];   // M2t[ci][k]
__device__ float g_c0[16];
__device__ float g_mu2[16];

// ===================== helpers =====================
__device__ __forceinline__ uint32_t smem_u32(const void* p) {
    uint32_t a;
    asm("{ .reg .u64 t; cvta.to.shared.u64 t, %1; cvt.u32.u64 %0, t; }" : "=r"(a) : "l"(p));
    return a;
}
__device__ __forceinline__ uint32_t swz128(uint32_t o) { return o ^ ((o >> 3) & 0x70); }

__device__ __forceinline__ void cp_async16(uint32_t dst, const void* src) {
    asm volatile("cp.async.cg.shared.global [%0], [%1], 16;" :: "r"(dst), "l"(src) : "memory");
}
#define CP_COMMIT() asm volatile("cp.async.commit_group;" ::: "memory")
#define CP_WAIT(n)  asm volatile("cp.async.wait_group %0;" :: "n"(n) : "memory")

#define LDSM_X4(r0, r1, r2, r3, addr) \
    asm volatile("ldmatrix.sync.aligned.m8n8.x4.shared.b16 {%0,%1,%2,%3}, [%4];" \
                 : "=r"(r0), "=r"(r1), "=r"(r2), "=r"(r3) : "r"(addr))

#define MMA16816(d, a, b0, b1) \
    asm volatile("mma.sync.aligned.m16n8k16.row.col.f32.f16.f16.f32 " \
                 "{%0,%1,%2,%3}, {%4,%5,%6,%7}, {%8,%9}, {%0,%1,%2,%3};" \
                 : "+f"((d)[0]), "+f"((d)[1]), "+f"((d)[2]), "+f"((d)[3]) \
                 : "r"((a)[0]), "r"((a)[1]), "r"((a)[2]), "r"((a)[3]), "r"(b0), "r"(b1))

__device__ __forceinline__ void split2(float v, __half& h0, __half& h1) {
    h0 = __float2half_rn(v);
    float r = v - __half2float(h0);
    h1 = __float2half_rn(r);
}
__device__ __forceinline__ uint32_t packh(__half lo, __half hi) {
    unsigned short a = *reinterpret_cast<unsigned short*>(&lo);
    unsigned short b = *reinterpret_cast<unsigned short*>(&hi);
    return (uint32_t)a | ((uint32_t)b << 16);
}

// ===================== merged prep: head tables + x split + w1/w2 split =====================
// grid 3920 blocks x 256:
//   [0,16)        : M2t (+ block 0: c0/mu2)
//   [16,1040)     : x split
//   [1040,1616)   : w1 split  (147456 elems)
//   [1616,3920)   : w2 split  (589824 elems)
__device__ __forceinline__ void prep_w_body(const float* __restrict__ w,
                                            __half* __restrict__ dst, int gid, int CIN) {
    const int NCC = CIN / 64;
    const size_t WPLANE = (size_t)256 * CIN * 9;
    if (gid >= (int)WPLANE) return;
    int tap = gid % 9, r = gid / 9;
    int ci = r % CIN, co = r / CIN;
    int dr = tap / 3, dc = tap % 3;
    int cic = ci >> 6, cj = ci & 63;
    int chunk = (dr * NCC + cic) * 3 + dc;
    size_t di = ((size_t)chunk * 256 + co) * 64 + cj;
    __half s0, s1;
    split2(w[gid], s0, s1);
    dst[di] = s0;
    dst[di + WPLANE] = s1;
}

__global__ void prep_all(const float* __restrict__ x,
                         const float* __restrict__ w1,
                         const float* __restrict__ w2,
                         const float* __restrict__ w3,
                         const float* __restrict__ b3,
                         const float* __restrict__ mu) {
    const int bx = blockIdx.x;
    const int tid = threadIdx.x;
    if (bx < 16) {
        const int p = bx * 256 + tid;  // p = ci*16 + k
        const int ci = p >> 4, k = p & 15;
        float s = 0.f;
        for (int co = 0; co < 256; ++co) s = fmaf(mu[k * 256 + co], w3[co * 256 + ci], s);
        g_M2t[p] = s;
        if (bx == 0 && tid < 16) {
            float sb = 0.f, m2 = 0.f;
            for (int c = 0; c < 256; ++c) {
                float mv = mu[tid * 256 + c];
                sb = fmaf(mv, b3[c], sb);
                m2 = fmaf(mv, mv, m2);
            }
            g_c0[tid] = sb;
            g_mu2[tid] = m2;
        }
    } else if (bx < 1040) {
        const int id = bx - 16;
        const int h = id & 255, b = id >> 8;
        const size_t XPLANE = 16908288;  // 4*256*258*64
        for (int idx = tid; idx < 258 * 64; idx += 256) {
            int w = idx >> 6, ci = idx & 63;
            int wsrc = min(max(w - 1, 0), WW - 1);
            float v = x[(((size_t)b * 64 + ci) * HH + h) * WW + wsrc];
            __half s0, s1;
            split2(v, s0, s1);
            size_t base = (((size_t)b * 256 + h) * 258 + w) * 64 + ci;
            g_xp[base] = s0;
            g_xp[base + XPLANE] = s1;
        }
    } else if (bx < 1616) {
        prep_w_body(w1, g_w1s, (bx - 1040) * 256 + tid, 64);
    } else {
        prep_w_body(w2, g_w2s, (bx - 1616) * 256 + tid, 256);
    }
}

// ===================== conv via mma.sync (fp16 2-split, 3 products) — R7 verbatim =====================
// grid (4 = 2 pxHalf x 2 coHalf, 256 h, 4 b), 256 threads (8 warps: 4M x 2N).
// K-chunks of 32ci, plane-packed rows [p0 32ci | p1 32ci]; ring-of-3 32KB buffers
// -> 2 CTAs/SM.  One __syncthreads per chunk.  ALL staging .cg.
template <int CIN, bool SPLIT_OUT>
__global__ __launch_bounds__(256, 2) void conv_mma(
    const __half* __restrict__ xp,   // [s][b][h][258][CIN]
    const __half* __restrict__ wsp,  // [s][chunk64][256][64]
    const float* __restrict__ bias,
    __half* __restrict__ out_split,  // [s][b][h][258][256]
    float* __restrict__ out_planar)  // [b][co][h][w]
{
    constexpr int NCC64 = CIN / 64;
    constexpr int NCC32 = CIN / 32;
    constexpr int NCH = 9 * NCC32;   // 18 or 72 chunks
    const size_t IPLANE = (size_t)4 * 256 * 258 * CIN;
    const size_t WPLANE = (size_t)(9 * NCC64) * 16384;
    const size_t OPLANE = (size_t)4 * 256 * 258 * 256;
    constexpr uint32_t BUFB = 32768;  // 16KB A + 16KB B

    extern __shared__ char smem_raw[];
    const uint32_t abase = (smem_u32(smem_raw) + 1023u) & ~1023u;

    const int tid = threadIdx.x;
    const int wid = tid >> 5, lane = tid & 31;
    const int warpM = wid & 3, warpN = wid >> 2;
    const int h = blockIdx.y, b = blockIdx.z;
    const int pxBase = (blockIdx.x & 1) * 128;
    const int coBase = (blockIdx.x >> 1) * 128;

    // stage one 32ci chunk (A + B), plane-packed rows
    auto stage = [&](int chunk, int buf) {
        int dc = chunk % 3;
        int r0 = chunk / 3;
        int cic32 = r0 % NCC32;
        int dr = r0 / NCC32;
        int hr = min(max(h + dr - 1, 0), HH - 1);
        const __half* xrow =
            xp + (((size_t)b * 256 + hr) * 258 + pxBase + dc) * CIN + cic32 * 32;
        uint32_t aoff = abase + (uint32_t)buf * BUFB;
        uint32_t boff = aoff + 16384;
#pragma unroll
        for (int t = 0; t < 4; ++t) {
            int idx = tid + (t << 8);
            int row = idx >> 3, sub = idx & 7;
            int plane = sub >> 2, seg = sub & 3;
            const void* src = xrow + (size_t)plane * IPLANE + (size_t)row * CIN + seg * 8;
            cp_async16(aoff + swz128((row << 7) | (plane << 6) | (seg << 4)), src);
        }
        int chunk64 = (dr * NCC64 + (cic32 >> 1)) * 3 + dc;
        const __half* wrow =
            wsp + ((size_t)chunk64 * 256 + coBase) * 64 + (cic32 & 1) * 32;
#pragma unroll
        for (int t = 0; t < 4; ++t) {
            int idx = tid + (t << 8);
            int co = idx >> 3, sub = idx & 7;
            int plane = sub >> 2, seg = sub & 3;
            const void* src = wrow + (size_t)plane * WPLANE + (size_t)co * 64 + seg * 8;
            cp_async16(boff + swz128((co << 7) | (plane << 6) | (seg << 4)), src);
        }
        CP_COMMIT();
    };

    float acc[2][8][4];
#pragma unroll
    for (int mt = 0; mt < 2; ++mt)
#pragma unroll
        for (int nt = 0; nt < 8; ++nt)
#pragma unroll
            for (int e = 0; e < 4; ++e) acc[mt][nt][e] = 0.f;

    const uint32_t rA = lane & 15, cA = (lane >> 4) << 4;
    const uint32_t rB = (lane & 7) | ((lane >> 4) << 3), cB = ((lane >> 3) & 1) << 4;

    // products: (a0,b0), (a0,b1), (a1,b0)
    const int SA[3] = {0, 0, 1};
    const int SB[3] = {0, 1, 0};

    stage(0, 0);
    stage(1, 1);

    for (int c = 0; c < NCH; ++c) {
        if (c + 1 < NCH) { CP_WAIT(1); } else { CP_WAIT(0); }
        __syncthreads();
        if (c + 2 < NCH) stage(c + 2, (c + 2) - ((c + 2) / 3) * 3);

        const uint32_t aB = abase + (uint32_t)(c - (c / 3) * 3) * BUFB;
        const uint32_t bB = aB + 16384;

#pragma unroll
        for (int ks = 0; ks < 2; ++ks) {
            uint32_t af[2][2][4];
#pragma unroll
            for (int plane = 0; plane < 2; ++plane)
#pragma unroll
                for (int mt = 0; mt < 2; ++mt) {
                    uint32_t row = warpM * 32 + mt * 16 + rA;
                    uint32_t addr =
                        aB + swz128((row << 7) + (plane << 6) + ks * 32 + cA);
                    LDSM_X4(af[plane][mt][0], af[plane][mt][1], af[plane][mt][2],
                            af[plane][mt][3], addr);
                }
#pragma unroll
            for (int np = 0; np < 4; ++np) {
                uint32_t bfr[2][4];
#pragma unroll
                for (int plane = 0; plane < 2; ++plane) {
                    uint32_t row = warpN * 64 + np * 16 + rB;
                    uint32_t addr =
                        bB + swz128((row << 7) + (plane << 6) + ks * 32 + cB);
                    LDSM_X4(bfr[plane][0], bfr[plane][1], bfr[plane][2], bfr[plane][3],
                            addr);
                }
#pragma unroll
                for (int t = 0; t < 3; ++t) {
                    const int sa = SA[t], sb = SB[t];
#pragma unroll
                    for (int mt = 0; mt < 2; ++mt) {
                        MMA16816(acc[mt][2 * np], af[sa][mt], bfr[sb][0], bfr[sb][1]);
                        MMA16816(acc[mt][2 * np + 1], af[sa][mt], bfr[sb][2], bfr[sb][3]);
                    }
                }
            }
        }
    }

    // ---- epilogue (R7-proven) ----
    float bv0[8], bv1[8];
#pragma unroll
    for (int nt = 0; nt < 8; ++nt) {
        int c0 = coBase + warpN * 64 + nt * 8 + (lane & 3) * 2;
        bv0[nt] = __ldg(bias + c0);
        bv1[nt] = __ldg(bias + c0 + 1);
    }

#pragma unroll
    for (int mt = 0; mt < 2; ++mt) {
#pragma unroll
        for (int nt = 0; nt < 8; ++nt) {
            int px0 = pxBase + warpM * 32 + mt * 16 + (lane >> 2);
            int c0 = coBase + warpN * 64 + nt * 8 + (lane & 3) * 2;
#pragma unroll
            for (int half = 0; half < 2; ++half) {
                int px = px0 + half * 8;
                float v0 = fmaxf(acc[mt][nt][2 * half] + bv0[nt], 0.f);
                float v1 = fmaxf(acc[mt][nt][2 * half + 1] + bv1[nt], 0.f);
                if (SPLIT_OUT) {
                    __half a0, a1, d0, d1;
                    split2(v0, a0, a1);
                    split2(v1, d0, d1);
                    uint32_t p0 = packh(a0, d0), p1 = packh(a1, d1);
                    size_t base = (((size_t)b * 256 + h) * 258 + px + 1) * 256 + c0;
                    *reinterpret_cast<uint32_t*>(out_split + base) = p0;
                    *reinterpret_cast<uint32_t*>(out_split + OPLANE + base) = p1;
                    if (px == 0 || px == 255) {
                        size_t hb =
                            (((size_t)b * 256 + h) * 258 + (px == 0 ? 0 : 257)) * 256 + c0;
                        *reinterpret_cast<uint32_t*>(out_split + hb) = p0;
                        *reinterpret_cast<uint32_t*>(out_split + OPLANE + hb) = p1;
                    }
                } else {
                    size_t o0 = ((size_t)b * 256 + c0) * HWTOT + h * WW + px;
                    out_planar[o0] = v0;
                    out_planar[o0 + HWTOT] = v1;
                }
            }
        }
    }
}

// ===================== head: cross-only + softmax, 4 px/thread float4 (R15 per-kernel win) =====
// grid (128, 4), 128 threads; px0 = blockIdx.x*512 + tid*4.
__global__ __launch_bounds__(128) void cross_head(
    const float* __restrict__ label, float* __restrict__ out)
{
    __shared__ __align__(16) float m2s[256][16];
    __shared__ float c2s[16], labs[16];

    const int tid = threadIdx.x;
    const int b = blockIdx.y;
    const int px0 = blockIdx.x * 512 + tid * 4;

    for (int i = tid; i < 4096; i += 128) m2s[i >> 4][i & 15] = g_M2t[i];
    if (tid < 16) {
        c2s[tid] = 2.f * g_c0[tid] - g_mu2[tid];
        labs[tid] = label[tid];
    }
    __syncthreads();

    const float* q2b = g_q2 + (size_t)b * 256 * HWTOT + px0;

    float acc[16][4];
#pragma unroll
    for (int k = 0; k < 16; ++k)
#pragma unroll
        for (int j = 0; j < 4; ++j) acc[k][j] = 0.f;

#pragma unroll 4
    for (int ci = 0; ci < 256; ++ci) {
        float4 v = *reinterpret_cast<const float4*>(q2b + (size_t)ci * HWTOT);
        float4 m0 = *reinterpret_cast<const float4*>(&m2s[ci][0]);
        float4 m1 = *reinterpret_cast<const float4*>(&m2s[ci][4]);
        float4 m2v = *reinterpret_cast<const float4*>(&m2s[ci][8]);
        float4 m3 = *reinterpret_cast<const float4*>(&m2s[ci][12]);
        float mm[16] = {m0.x, m0.y, m0.z, m0.w, m1.x, m1.y, m1.z, m1.w,
                        m2v.x, m2v.y, m2v.z, m2v.w, m3.x, m3.y, m3.z, m3.w};
#pragma unroll
        for (int k = 0; k < 16; ++k) {
            acc[k][0] = fmaf(v.x, mm[k], acc[k][0]);
            acc[k][1] = fmaf(v.y, mm[k], acc[k][1]);
            acc[k][2] = fmaf(v.z, mm[k], acc[k][2]);
            acc[k][3] = fmaf(v.w, mm[k], acc[k][3]);
        }
    }

    float res[4];
#pragma unroll
    for (int j = 0; j < 4; ++j) {
        float lg[16];
        float mx = -1e30f;
#pragma unroll
        for (int k = 0; k < 16; ++k) {
            lg[k] = fmaf(2.f, acc[k][j], c2s[k]);
            mx = fmaxf(mx, lg[k]);
        }
        float se = 0.f, sl = 0.f;
#pragma unroll
        for (int k = 0; k < 16; ++k) {
            float e = __expf(lg[k] - mx);
            se += e;
            sl = fmaf(e, labs[k], sl);
        }
        res[j] = sl / se;
    }
    *reinterpret_cast<float4*>(out + (size_t)b * HWTOT + px0) =
        make_float4(res[0], res[1], res[2], res[3]);
}

// ===================== launch =====================
extern "C" void kernel_launch(void* const* d_in, const int* in_sizes, int n_in,
                              void* d_out, int out_size) {
    const float* x = (const float*)d_in[0];
    const float* w1 = (const float*)d_in[1];
    const float* b1 = (const float*)d_in[2];
    const float* w2 = (const float*)d_in[3];
    const float* b2 = (const float*)d_in[4];
    const float* w3 = (const float*)d_in[5];
    const float* b3 = (const float*)d_in[6];
    const float* mu = (const float*)d_in[7];
    const float* label = (const float*)d_in[8];
    float* out = (float*)d_out;

    __half *xp, *q1p, *w1s, *w2s;
    float* q2;
    cudaGetSymbolAddress((void**)&xp, g_xp);
    cudaGetSymbolAddress((void**)&q1p, g_q1p);
    cudaGetSymbolAddress((void**)&q2, g_q2);
    cudaGetSymbolAddress((void**)&w1s, g_w1s);
    cudaGetSymbolAddress((void**)&w2s, g_w2s);

    const int SMEM_BYTES = 3 * 32768 + 1024;  // 97 KB -> 2 CTAs/SM
    cudaFuncSetAttribute(conv_mma<64, true>, cudaFuncAttributeMaxDynamicSharedMemorySize,
                         SMEM_BYTES);
    cudaFuncSetAttribute(conv_mma<256, false>, cudaFuncAttributeMaxDynamicSharedMemorySize,
                         SMEM_BYTES);

    prep_all<<<3920, 256>>>(x, w1, w2, w3, b3, mu);

    dim3 cgrid(4, 256, 4);
    conv_mma<64, true><<<cgrid, 256, SMEM_BYTES>>>(xp, w1s, b1, q1p, nullptr);
    conv_mma<256, false><<<cgrid, 256, SMEM_BYTES>>>(q1p, w2s, b2, nullptr, q2);

    cross_head<<<dim3(128, 4), 128>>>(label, out);  // 128 blk * 128 thr * 4 px == HWTOT
}